// round 17
// baseline (speedup 1.0000x reference)
#include <cuda_runtime.h>
#include <cuda_bf16.h>
#include <cstdint>

#define NN 10000
#define RP 16
#define EE 64
#define NTT 8000
#define RR 8000
#define CC 16
#define NREL 50

__device__ __forceinline__ uint32_t smem_u32(const void* p) {
    uint32_t a;
    asm("{ .reg .u64 t; cvta.to.shared.u64 t, %1; cvt.u32.u64 %0, t; }" : "=r"(a) : "l"(p));
    return a;
}

#define LDSM_X4(r, a) \
    asm volatile("ldmatrix.sync.aligned.m8n8.x4.shared.b16 {%0,%1,%2,%3}, [%4];" \
        : "=r"((r)[0]), "=r"((r)[1]), "=r"((r)[2]), "=r"((r)[3]) : "r"(a))
#define LDSM_X4_T(r, a) \
    asm volatile("ldmatrix.sync.aligned.m8n8.x4.trans.shared.b16 {%0,%1,%2,%3}, [%4];" \
        : "=r"((r)[0]), "=r"((r)[1]), "=r"((r)[2]), "=r"((r)[3]) : "r"(a))
#define MMA_BF16(c, a, b0, b1) \
    asm volatile("mma.sync.aligned.m16n8k16.row.col.f32.bf16.bf16.f32 " \
        "{%0,%1,%2,%3}, {%4,%5,%6,%7}, {%8,%9}, {%0,%1,%2,%3};" \
        : "+f"((c)[0]), "+f"((c)[1]), "+f"((c)[2]), "+f"((c)[3]) \
        : "r"((a)[0]), "r"((a)[1]), "r"((a)[2]), "r"((a)[3]), "r"(b0), "r"(b1))

// ---- static scratch (no allocations) ----
__device__ float g_T1[NREL * RP];
__device__ float g_T2[NREL * RP];
__device__ int   g_p[NTT];
__device__ float g_colsum[NN * RP];
__device__ float g_rowsum[NN * RP];
__device__ float g_h[NN * EE];
__device__ float g_P[NN * RP * CC];     // P[n][r2*16+c]
__device__ uint32_t g_Bhi[8192];        // pre-split B, swizzled smem image (32KB)
__device__ uint32_t g_Blo[8192];

// K0: zero sums/h, init out = bias2; blocks 0..49 build latent tables;
// blocks 50..81 pre-split weights2 into bf16 hi/lo swizzled images.
__global__ void k_zero(const float* __restrict__ bias2, float* __restrict__ out,
                       const float* __restrict__ w1a, const float* __restrict__ b1a,
                       const float* __restrict__ w1b, const float* __restrict__ b1b,
                       const float* __restrict__ w2a, const float* __restrict__ b2a,
                       const float* __restrict__ w2b, const float* __restrict__ b2b,
                       const float* __restrict__ w2) {
    int i = blockIdx.x * blockDim.x + threadIdx.x;
    if (i < NN * RP) { g_colsum[i] = 0.f; g_rowsum[i] = 0.f; }
    if (i < NN * EE) g_h[i] = 0.f;
    if (i < NN * CC) out[i] = bias2[i & (CC - 1)];

    if (blockIdx.x >= 50 && blockIdx.x < 82) {
        int pp = (blockIdx.x - 50) * 256 + threadIdx.x;   // 0..8191
        int idx = pp * 2;
        int c = idx & 15;
        int k = (idx >> 4) & 63;
        int r2 = idx >> 10;
        int n = r2 * 16 + c;
        float2 v = *(const float2*)&w2[idx];
        __nv_bfloat16 h0 = __float2bfloat16(v.x);
        __nv_bfloat16 h1 = __float2bfloat16(v.y);
        __nv_bfloat16 l0 = __float2bfloat16(v.x - __bfloat162float(h0));
        __nv_bfloat16 l1 = __float2bfloat16(v.y - __bfloat162float(h1));
        uint32_t hi = (uint32_t)*(uint16_t*)&h0 | ((uint32_t)*(uint16_t*)&h1 << 16);
        uint32_t lo = (uint32_t)*(uint16_t*)&l0 | ((uint32_t)*(uint16_t*)&l1 << 16);
        uint32_t off = (uint32_t)(k * 512) + (((uint32_t)(2 * n)) ^ ((uint32_t)(k & 7) << 4));
        g_Bhi[off >> 2] = hi;
        g_Blo[off >> 2] = lo;
    }

    if (blockIdx.x < NREL && threadIdx.x < 32) {
        int p = blockIdx.x;
        int lane = threadIdx.x;
        float a0 = fmaxf(w1a[p * EE + lane] + b1a[lane], 0.f);
        float a1 = fmaxf(w1a[p * EE + 32 + lane] + b1a[32 + lane], 0.f);
        float c0 = fmaxf(w2a[p * EE + lane] + b2a[lane], 0.f);
        float c1 = fmaxf(w2a[p * EE + 32 + lane] + b2a[32 + lane], 0.f);
        float y1[RP], y2[RP];
#pragma unroll
        for (int r = 0; r < RP; r++) {
            y1[r] = a0 * w1b[lane * RP + r] + a1 * w1b[(lane + 32) * RP + r];
            y2[r] = c0 * w2b[lane * RP + r] + c1 * w2b[(lane + 32) * RP + r];
        }
#pragma unroll
        for (int off = 16; off >= 1; off >>= 1) {
#pragma unroll
            for (int r = 0; r < RP; r++) {
                y1[r] += __shfl_xor_sync(0xffffffffu, y1[r], off);
                y2[r] += __shfl_xor_sync(0xffffffffu, y2[r], off);
            }
        }
        float m1 = -1e30f, m2 = -1e30f;
#pragma unroll
        for (int r = 0; r < RP; r++) {
            y1[r] += b1b[r]; y2[r] += b2b[r];
            m1 = fmaxf(m1, y1[r]); m2 = fmaxf(m2, y2[r]);
        }
        float s1 = 0.f, s2 = 0.f, e1 = 0.f, e2 = 0.f;
#pragma unroll
        for (int r = 0; r < RP; r++) {
            float t1 = __expf(y1[r] - m1), t2 = __expf(y2[r] - m2);
            s1 += t1; s2 += t2;
            if (lane == r) { e1 = t1; e2 = t2; }
        }
        if (lane < RP) {
            g_T1[p * RP + lane] = e1 / s1;
            g_T2[p * RP + lane] = e2 / s2;
        }
    }
}

// K2: find p[t]; accumulate colsum/rowsum (index-0 hotspot pre-reduced).
__global__ void k_sums(const float* __restrict__ nhots, const int* __restrict__ hind) {
    int t = blockIdx.x * blockDim.x + threadIdx.x;
    float c0 = 0.f, r0 = 0.f;
    if (t < NTT) {
        const float4* row4 = (const float4*)(nhots + (size_t)t * RR);
        int p = 0;
#pragma unroll
        for (int j = 0; j < 12; j++) {
            float4 v = row4[j];
            if (v.x != 0.f) p = 4 * j;
            if (v.y != 0.f) p = 4 * j + 1;
            if (v.z != 0.f) p = 4 * j + 2;
            if (v.w != 0.f) p = 4 * j + 3;
        }
        {
            float4 v = row4[12];
            if (v.x != 0.f) p = 48;
            if (v.y != 0.f) p = 49;
        }
        g_p[t] = p;
        int s = hind[2 * (NTT + t)];
        int o = hind[2 * (NTT + t) + 1];
#pragma unroll
        for (int r = 0; r < RP; r++) {
            float l1 = g_T1[p * RP + r], l2 = g_T2[p * RP + r];
            int ic = o * r, ir = s * r;
            if (ic) atomicAdd(&g_colsum[ic], l1); else c0 += l1;
            if (ir) atomicAdd(&g_rowsum[ir], l2); else r0 += l2;
        }
    }
#pragma unroll
    for (int off = 16; off >= 1; off >>= 1) {
        c0 += __shfl_xor_sync(0xffffffffu, c0, off);
        r0 += __shfl_xor_sync(0xffffffffu, r0, off);
    }
    if ((threadIdx.x & 31) == 0) {
        if (c0 != 0.f) atomicAdd(&g_colsum[0], c0);
        if (r0 != 0.f) atomicAdd(&g_rowsum[0], r0);
    }
}

// K3: h[s] += (L1/colsum)*weights1_flat[o*r]. Warp per t.
__global__ void k_hacc(const int* __restrict__ hind, const float* __restrict__ w1) {
    __shared__ float sT1[NREL * RP];
    for (int i = threadIdx.x; i < NREL * RP; i += blockDim.x) sT1[i] = g_T1[i];
    __syncthreads();
    int warp = threadIdx.x >> 5, lane = threadIdx.x & 31;
    int t = blockIdx.x * 8 + warp;
    int half = lane >> 4;
    int q = lane & 15;
    int p = g_p[t];
    int s = hind[2 * (NTT + t)];
    int o = hind[2 * (NTT + t) + 1];
    float ax = 0.f, ay = 0.f, az = 0.f, aw = 0.f;
#pragma unroll
    for (int i = 0; i < 8; i++) {
        int r = 2 * i + half;
        int idx = o * r;
        float w = __fdividef(sT1[p * RP + r], g_colsum[idx]);
        float4 v = ((const float4*)(w1 + (size_t)idx * EE))[q];
        ax += w * v.x; ay += w * v.y; az += w * v.z; aw += w * v.w;
    }
    ax += __shfl_xor_sync(0xffffffffu, ax, 16);
    ay += __shfl_xor_sync(0xffffffffu, ay, 16);
    az += __shfl_xor_sync(0xffffffffu, az, 16);
    aw += __shfl_xor_sync(0xffffffffu, aw, 16);
    if (half == 0) {
        float* dst = &g_h[s * EE + q * 4];
        atomicAdd(dst + 0, ax);
        atomicAdd(dst + 1, ay);
        atomicAdd(dst + 2, az);
        atomicAdd(dst + 3, aw);
    }
}

// K5: P = relu(h+bias1)(10000x64) @ B(64x256) via mma.sync bf16-split HMMA.
// Tile M=64, N=256, K=64. 8 warps: rw = wid>>1 (rows rw*16..+15),
// cw = wid&1 (cols cw*128..+127, 16 n-tiles). B copied pre-split from gmem.
#define SMB_A_HI 0
#define SMB_A_LO 8192
#define SMB_B_HI 16384
#define SMB_B_LO (16384 + 32768)
#define SM_TOTAL (16384 + 65536)

__global__ __launch_bounds__(256) void k_gemm(const float* __restrict__ bias1) {
    extern __shared__ char sm[];
    uint32_t base = smem_u32(sm);
    int tid = threadIdx.x;
    int rb = blockIdx.x;

    // ---- B tiles: straight float4 copy of pre-split swizzled images
#pragma unroll
    for (int it = 0; it < 8; it++) {
        int idx4 = it * 256 + tid;                // 2048 float4 per buffer
        float4 v = *(const float4*)&g_Bhi[idx4 * 4];
        *(float4*)(sm + SMB_B_HI + idx4 * 16) = v;
        float4 w = *(const float4*)&g_Blo[idx4 * 4];
        *(float4*)(sm + SMB_B_LO + idx4 * 16) = w;
    }

    // ---- A tile: 64 rows, relu(h+bias1) fused; 4 threads/row, 16 k each
    {
        int r = tid >> 2;
        int kq = (tid & 3) * 16;
        int m = rb * 64 + r;
        float vv[16];
        if (m < NN) {
#pragma unroll
            for (int q = 0; q < 4; q++) {
                float4 x = *(const float4*)&g_h[m * 64 + kq + q * 4];
                float4 b = *(const float4*)&bias1[kq + q * 4];
                vv[q * 4 + 0] = fmaxf(x.x + b.x, 0.f);
                vv[q * 4 + 1] = fmaxf(x.y + b.y, 0.f);
                vv[q * 4 + 2] = fmaxf(x.z + b.z, 0.f);
                vv[q * 4 + 3] = fmaxf(x.w + b.w, 0.f);
            }
        } else {
#pragma unroll
            for (int e = 0; e < 16; e++) vv[e] = 0.f;
        }
#pragma unroll
        for (int pj = 0; pj < 8; pj++) {
            int k = kq + 2 * pj;
            __nv_bfloat16 h0 = __float2bfloat16(vv[2 * pj]);
            __nv_bfloat16 h1 = __float2bfloat16(vv[2 * pj + 1]);
            __nv_bfloat16 l0 = __float2bfloat16(vv[2 * pj] - __bfloat162float(h0));
            __nv_bfloat16 l1 = __float2bfloat16(vv[2 * pj + 1] - __bfloat162float(h1));
            uint32_t hi = (uint32_t)*(uint16_t*)&h0 | ((uint32_t)*(uint16_t*)&h1 << 16);
            uint32_t lo = (uint32_t)*(uint16_t*)&l0 | ((uint32_t)*(uint16_t*)&l1 << 16);
            uint32_t off = (uint32_t)(r * 128) + (((uint32_t)(2 * k)) ^ ((uint32_t)(r & 7) << 4));
            *(uint32_t*)(sm + SMB_A_HI + off) = hi;
            *(uint32_t*)(sm + SMB_A_LO + off) = lo;
        }
    }
    __syncthreads();

    int wid = tid >> 5, lane = tid & 31;
    int rw = wid >> 1, cw = wid & 1;
    int mbase = rw * 16;
    int g = lane >> 3, i = lane & 7;

    float acc[16][4];
#pragma unroll
    for (int nt = 0; nt < 16; nt++)
#pragma unroll
        for (int e = 0; e < 4; e++) acc[nt][e] = 0.f;

#pragma unroll
    for (int ks = 0; ks < 4; ks++) {
        int k0 = ks * 16;
        uint32_t arow = (uint32_t)(mbase + (g & 1) * 8 + i);
        uint32_t abyte = (uint32_t)(k0 * 2 + (g >> 1) * 16);
        uint32_t aoff = arow * 128 + (abyte ^ ((arow & 7) << 4));
        uint32_t ah[4], al[4];
        LDSM_X4(ah, base + SMB_A_HI + aoff);
        LDSM_X4(al, base + SMB_A_LO + aoff);
#pragma unroll
        for (int tp = 0; tp < 8; tp++) {
            int n0 = cw * 128 + tp * 16;
            uint32_t krow = (uint32_t)(k0 + (g & 1) * 8 + i);
            uint32_t nbyte = (uint32_t)((n0 + (g >> 1) * 8) * 2);
            uint32_t boff = krow * 512 + (nbyte ^ ((krow & 7) << 4));
            uint32_t bh[4], bl[4];
            LDSM_X4_T(bh, base + SMB_B_HI + boff);
            LDSM_X4_T(bl, base + SMB_B_LO + boff);
            MMA_BF16(acc[2 * tp],     ah, bh[0], bh[1]);
            MMA_BF16(acc[2 * tp + 1], ah, bh[2], bh[3]);
            MMA_BF16(acc[2 * tp],     ah, bl[0], bl[1]);
            MMA_BF16(acc[2 * tp + 1], ah, bl[2], bl[3]);
            MMA_BF16(acc[2 * tp],     al, bh[0], bh[1]);
            MMA_BF16(acc[2 * tp + 1], al, bh[2], bh[3]);
        }
    }

    // Epilogue
    {
        int r0 = rb * 64 + mbase + (lane >> 2);
        int cb0 = cw * 128 + 2 * (lane & 3);
#pragma unroll
        for (int nt = 0; nt < 16; nt++) {
            int col = cb0 + nt * 8;
            if (r0 < NN)
                *(float2*)&g_P[(size_t)r0 * 256 + col] = make_float2(acc[nt][0], acc[nt][1]);
            if (r0 + 8 < NN)
                *(float2*)&g_P[(size_t)(r0 + 8) * 256 + col] = make_float2(acc[nt][2], acc[nt][3]);
        }
    }
}

// K6: out[np,c] += (L2/rowsum)*P[o,r2,c]. 16 lanes (c) per t, 16 t per block.
__global__ void k_scatter(const int* __restrict__ hind, float* __restrict__ out) {
    __shared__ float sT2[NREL * RP];
    __shared__ float red[256];
    for (int i = threadIdx.x; i < NREL * RP; i += 256) sT2[i] = g_T2[i];
    __syncthreads();
    int tid = threadIdx.x;
    int tt = tid >> 4, c = tid & 15;
    int half = tt & 1;
    int t = blockIdx.x * 16 + tt;
    int p = g_p[t];
    int s = hind[2 * (NTT + t)];
    int o = hind[2 * (NTT + t) + 1];
    float w_mine = __fdividef(sT2[p * RP + c], g_rowsum[s * c]);
    const float* Po = g_P + (size_t)o * 256;
    float pv[RP];
#pragma unroll
    for (int r2 = 0; r2 < RP; r2++) pv[r2] = Po[r2 * 16 + c];

    float acc0 = 0.f;
#pragma unroll
    for (int r = 0; r < RP; r++) {
        float w = __shfl_sync(0xffffffffu, w_mine, half * 16 + r);
        int flat = s * r;
        int r2 = flat / NN;
        int np = flat - r2 * NN;
        float val = w * pv[r2];
        if (flat == 0) acc0 += val;
        else atomicAdd(&out[np * CC + c], val);
    }
    red[tid] = acc0;
    __syncthreads();
    if (tt == 0) {
        float ssum = 0.f;
#pragma unroll
        for (int i = 0; i < 16; i++) ssum += red[i * 16 + c];
        atomicAdd(&out[c], ssum);
    }
}

extern "C" void kernel_launch(void* const* d_in, const int* in_sizes, int n_in,
                              void* d_out, int out_size) {
    const float* nhots = (const float*)d_in[0];
    const float* w1a = (const float*)d_in[1];
    const float* b1a = (const float*)d_in[2];
    const float* w1b = (const float*)d_in[3];
    const float* b1b = (const float*)d_in[4];
    const float* w2a = (const float*)d_in[5];
    const float* b2a = (const float*)d_in[6];
    const float* w2b = (const float*)d_in[7];
    const float* b2b = (const float*)d_in[8];
    const float* weights1 = (const float*)d_in[9];
    const float* bias1 = (const float*)d_in[10];
    const float* weights2 = (const float*)d_in[11];
    const float* bias2 = (const float*)d_in[12];
    const int* hind = (const int*)d_in[13];
    float* out = (float*)d_out;

    cudaFuncSetAttribute(k_gemm, cudaFuncAttributeMaxDynamicSharedMemorySize, SM_TOTAL);

    k_zero<<<(NN * EE + 255) / 256, 256>>>(bias2, out, w1a, b1a, w1b, b1b,
                                           w2a, b2a, w2b, b2b, weights2);
    k_sums<<<(NTT + 255) / 256, 256>>>(nhots, hind);
    k_hacc<<<NTT / 8, 256>>>(hind, weights1);
    k_gemm<<<(NN + 63) / 64, 256, SM_TOTAL>>>(bias1);
    k_scatter<<<NTT / 16, 256>>>(hind, out);
}